// round 3
// baseline (speedup 1.0000x reference)
#include <cuda_runtime.h>

// MaxOccurrencePool: sliding-window (K=9) mode-with-tie-average + max-count over
// integer values 0..4 (values 1..4 counted, bin0 only when window empty).
// x: [B=8, L=131072, C=16] f32. Outputs: out [B, L-1, C] f32, then density [B, L-1, C] f32.
//
// R3: exactly-one-wave grid. Reg limit gives 8 CTAs/SM -> 1184 CTA capacity;
//     U=28 positions/warp -> 4682 warps -> 1171 CTAs: single balanced wave
//     (R2's 1821 CTAs = 1.54 waves; the half-empty 2nd wave capped DRAM at 55%).
//     28 = 3*9 + 1: three unrolled ring groups + one epilogue step at slot 0.

#define BB    8
#define LL    131072
#define LOUT  131071               // L - 1 output positions
#define U     28                   // positions per warp
#define NWARP ((LOUT + U - 1) / U) // 4682
#define NBLK  ((NWARP + 3) / 4)    // 1171 CTAs <= 1184 (one wave at 8 CTA/SM)

// one-hot byte delta for value iv in 0..4: byte (iv-1) = 1, or 0 for iv==0.
__device__ __forceinline__ unsigned dsh(unsigned iv) {
    return __funnelshift_lc(0x01000000u, 0u, iv << 3);
}

// h = packed byte counts (c1..c4) -> out (tie-averaged argmax) + density.
__device__ __forceinline__ void consume(unsigned h, float &outv, float &den) {
    unsigned c1 = h & 0xFFu;
    unsigned c2 = (h >> 8) & 0xFFu;
    unsigned c3 = (h >> 16) & 0xFFu;
    unsigned c4 = h >> 24;
    unsigned m  = max(max(c1, c2), max(c3, c4));
    unsigned y   = (h + 0x10101010u) - m * 0x01010101u;  // tied bytes carry into bit4
    unsigned msk = y & 0x10101010u;                      // 0x10 per tied byte
    unsigned s16 = __dp4a(msk, 0x04030201u, 0u);         // 16 * sum(tied indices)
    unsigned n16 = __dp4a(msk, 0x01010101u, 0u);         // 16 * num ties
    float o = __fdividef((float)s16, (float)n16);
    outv = (m == 0u) ? 0.0f : o;                         // empty window -> bin0 -> 0
    den  = (float)max(m, 1u);                            // empty window -> density 1
}

template <bool FULL>
__device__ __forceinline__ void step(int l, int ji, int lend,
                                     const float4 *__restrict__ xin,
                                     float4 *__restrict__ outp,
                                     float4 *__restrict__ denp,
                                     unsigned &h0, unsigned &h1,
                                     unsigned &h2, unsigned &h3,
                                     unsigned ring[9], float4 &cur) {
    unsigned i0 = (unsigned)(int)cur.x, i1 = (unsigned)(int)cur.y;
    unsigned i2 = (unsigned)(int)cur.z, i3 = (unsigned)(int)cur.w;

    // prefetch next incoming element (position l+6)
    float4 nxt = make_float4(0.f, 0.f, 0.f, 0.f);
    int pn = l + 6;
    if (FULL) {
        nxt = xin[pn * 4];
    } else if ((unsigned)pn < (unsigned)LL) {
        nxt = xin[pn * 4];
    }

    unsigned old = ring[ji];
    ring[ji] = i0 | (i1 << 4) | (i2 << 8) | (i3 << 12);

    // outgoing one-hot recomputed from packed nibbles: amt = nib*8
    unsigned od0 = __funnelshift_lc(0x01000000u, 0u, (old << 3) & 0x78u);
    unsigned od1 = __funnelshift_lc(0x01000000u, 0u, (old >> 1) & 0x78u);
    unsigned od2 = __funnelshift_lc(0x01000000u, 0u, (old >> 5) & 0x78u);
    unsigned od3 = __funnelshift_lc(0x01000000u, 0u, (old >> 9) & 0x78u);

    h0 += dsh(i0) - od0;
    h1 += dsh(i1) - od1;
    h2 += dsh(i2) - od2;
    h3 += dsh(i3) - od3;

    float4 o, dn;
    consume(h0, o.x, dn.x);
    consume(h1, o.y, dn.y);
    consume(h2, o.z, dn.z);
    consume(h3, o.w, dn.w);

    if (FULL || l < lend) {
        __stcs(&outp[l * 4], o);
        __stcs(&denp[l * 4], dn);
    }
    cur = nxt;
}

template <bool FULL>
__device__ __forceinline__ void run_chunk(const float4 *__restrict__ xin,
                                          float4 *__restrict__ outp,
                                          float4 *__restrict__ denp,
                                          int l0, int lend) {
    unsigned h0 = 0, h1 = 0, h2 = 0, h3 = 0;
    unsigned ring[9];                 // nibble-packed raw values of 4 channels

    // Prefill with positions p = l0-4 .. l0+4. OOB (padding) -> value 0.
    #pragma unroll
    for (int k = 0; k < 9; k++) {
        int p = l0 - 4 + k;
        float4 v = make_float4(0.f, 0.f, 0.f, 0.f);
        if ((unsigned)p < (unsigned)LL) v = xin[p * 4];
        unsigned i0 = (unsigned)(int)v.x, i1 = (unsigned)(int)v.y;
        unsigned i2 = (unsigned)(int)v.z, i3 = (unsigned)(int)v.w;
        ring[k] = i0 | (i1 << 4) | (i2 << 8) | (i3 << 12);
        h0 += dsh(i0); h1 += dsh(i1); h2 += dsh(i2); h3 += dsh(i3);
    }

    float4 cur = make_float4(0.f, 0.f, 0.f, 0.f);
    {
        int p = l0 + 5;
        if (FULL || (unsigned)p < (unsigned)LL) cur = xin[p * 4];
    }

    // 27 = 3 full ring periods, slots compile-time constant; then 1 epilogue (slot 0).
    #pragma unroll 1
    for (int jo = 0; jo < 3; jo++) {
        #pragma unroll
        for (int ji = 0; ji < 9; ji++)
            step<FULL>(l0 + jo * 9 + ji, ji, lend, xin, outp, denp,
                       h0, h1, h2, h3, ring, cur);
    }
    step<FULL>(l0 + 27, 0, lend, xin, outp, denp, h0, h1, h2, h3, ring, cur);
}

__global__ void __launch_bounds__(128, 8)
MaxOccurrencePool_kernel(const float *__restrict__ x, float *__restrict__ out) {
    int t = blockIdx.x * 128 + threadIdx.x;
    int wid = t >> 5;
    if (wid >= NWARP) return;
    int lane = t & 31;
    int cg = lane & 3;        // channel group (4 floats)
    int b  = lane >> 2;       // batch
    int l0 = wid * U;
    int lend = min(l0 + U, LOUT);

    const float4 *xin = reinterpret_cast<const float4 *>(x) + (size_t)b * LL * 4 + cg;
    float4 *outp = reinterpret_cast<float4 *>(out) + (size_t)b * LOUT * 4 + cg;
    float4 *denp = outp + (size_t)BB * LOUT * 4;   // density tensor follows out

    // FULL iff every touched index is in range: max read l0+27+6, all 28 stored
    if (l0 + U + 5 < LL && lend == l0 + U)
        run_chunk<true>(xin, outp, denp, l0, lend);
    else
        run_chunk<false>(xin, outp, denp, l0, lend);
}

extern "C" void kernel_launch(void* const* d_in, const int* in_sizes, int n_in,
                              void* d_out, int out_size) {
    const float *x = (const float *)d_in[0];
    float *out = (float *)d_out;
    MaxOccurrencePool_kernel<<<NBLK, 128>>>(x, out);
}